// round 15
// baseline (speedup 1.0000x reference)
#include <cuda_runtime.h>
#include <stdint.h>

// Problem shape (fixed by the dataset)
#define BATCH   8192
#define IN_DIM  4096
#define N_RULES 2048
#define NQ      4                // rule quarters (512 rules)
#define SPLITS  512              // pseudo-splits of 8 k-rows each
#define NWP     1024             // wpart blocks: 4 quarters x 256 (16 rows each)
#define NOUT    1024             // out tiles: 64 rg32 x 16 row-slices

// Scratch (device globals — no allocation allowed).
// g_part[s][r] = 1 iff any W[k,r] > 0.5 for k in pseudo-split s (8 rows).
// Fully overwritten every call. Counters are self-resetting (see below).
__device__ uint8_t  g_part[SPLITS * N_RULES];    // 1 MB
__device__ unsigned g_qdone[NQ];                 // wpart blocks done per quarter
__device__ unsigned g_alldone;                   // out tiles done (reset trigger)

// Cold path: recompute out[b,r] directly from W and x. Early-exits.
__device__ __noinline__ float conj_direct(const float* __restrict__ W,
                                          const float* __restrict__ x,
                                          int b, int r) {
    const float* xb = x + (size_t)b * IN_DIM;
    for (int k = 0; k < IN_DIM; k++) {
        if (W[(size_t)k * N_RULES + r] > 0.5f && xb[k] != 1.0f) return 0.0f;
    }
    return 1.0f;
}

// ---------------------------------------------------------------------------
// Fused kernel, 2048 blocks dispatched in id order:
//   ids [0, 1024):    wpart (quarter-major): block (qt, j) reads 16 k-rows x
//                     512 rules of W — 8 independent coalesced float4 loads
//                     per thread, register OR, one uchar4 store. Never waits.
//   ids [1024, 2048): out tile (quarter-major): waits on g_qdone[qt] == 256
//                     (all of that quarter's wpart ids are strictly smaller,
//                     and HW dispatches blocks in id order -> no deadlock).
// Overlap: quarter 0's W read (~1.5us) completes while later wpart blocks
// stream; out writes then run concurrently with the remaining W reads.
// ---------------------------------------------------------------------------
__global__ void __launch_bounds__(256)
fused_kernel(const float* __restrict__ W, const float* __restrict__ x,
             float* __restrict__ out) {
    __shared__ uint32_t sm_red[8][32];
    __shared__ __align__(16) float s_val[32];
    __shared__ uint32_t s_w[32];
    __shared__ uint32_t s_flag;
    int tid = threadIdx.x;

    if (blockIdx.x < NWP) {
        // ------------- wpart: (quarter qt, row-block j) -------------------
        int qt = blockIdx.x >> 8;            // quarter [0, 4)
        int j  = blockIdx.x & 255;           // 16-row block within quarter
        int c4 = (tid & 127);                // float4 column within quarter
        int rh = tid >> 7;                   // row half (8 rows each)
        int sp = j * 2 + rh;                 // pseudo-split [0, 512)

        const float4* W4 = reinterpret_cast<const float4*>(W);
        size_t base = (size_t)(j * 16 + rh * 8) * (N_RULES / 4) + qt * 128 + c4;
        bool a0 = false, a1 = false, a2 = false, a3 = false;
#pragma unroll
        for (int i = 0; i < 8; i++) {        // 8 independent coalesced loads
            float4 v = W4[base + (size_t)i * (N_RULES / 4)];
            a0 |= (v.x > 0.5f);
            a1 |= (v.y > 0.5f);
            a2 |= (v.z > 0.5f);
            a3 |= (v.w > 0.5f);
        }
        uchar4 rb; rb.x = a0; rb.y = a1; rb.z = a2; rb.w = a3;
        reinterpret_cast<uchar4*>(g_part)[(size_t)sp * (N_RULES / 4) +
                                          qt * 128 + c4] = rb;
        __threadfence();                     // release g_part stores
        __syncthreads();
        if (tid == 0) atomicAdd(&g_qdone[qt], 1u);
    } else {
        // ------------- out tile: 32 rules x 512 rows ----------------------
        int q     = blockIdx.x - NWP;
        int qt    = q >> 8;                  // quarter
        int rem   = q & 255;
        int rg    = qt * 16 + (rem & 15);    // 32-rule group [0, 64)
        int slice = rem >> 4;
        int b0    = slice * 512;

        if (tid == 0) {                      // acquire this quarter's wparts
            while (((volatile unsigned*)g_qdone)[qt] < 256u) __nanosleep(32);
            __threadfence();
        }
        __syncthreads();

        {   // fold empties over 512 pseudo-splits (L2-resident, 16KB/block)
            int lane = tid & 31, wi = tid >> 5;
            uint32_t acc = 0;
#pragma unroll 8
            for (int i = 0; i < 64; i++) {
                acc |= g_part[(size_t)(wi * 64 + i) * N_RULES + rg * 32 + lane];
            }
            sm_red[wi][lane] = acc;
        }
        __syncthreads();
        if (tid < 32) {
            uint32_t o = sm_red[0][tid] | sm_red[1][tid] | sm_red[2][tid] |
                         sm_red[3][tid] | sm_red[4][tid] | sm_red[5][tid] |
                         sm_red[6][tid] | sm_red[7][tid];
            s_w[tid]   = o;
            s_val[tid] = (o == 0u) ? 1.0f : 0.0f;
            uint32_t any = __reduce_or_sync(0xFFFFFFFFu, o);
            if (tid == 0) s_flag = (any == 0u) ? 1u : 0u;
        }
        __syncthreads();

        bool empty  = (s_flag != 0u);
        int  chunk  = tid & 7;               // float4 chunk within 32 rules
        int  rowoff = tid >> 3;              // 0..31
        float4 v0 = *reinterpret_cast<const float4*>(s_val + chunk * 4);
        float4* o4 = reinterpret_cast<float4*>(out);
#pragma unroll
        for (int it = 0; it < 16; it++) {
            int b = b0 + it * 32 + rowoff;
            float4 o;
            if (empty) {
                o = v0;                      // dominant path: all rules empty
            } else {
                int r0 = rg * 32 + chunk * 4;
                o.x = (s_w[chunk*4+0] == 0u) ? 1.0f : conj_direct(W, x, b, r0+0);
                o.y = (s_w[chunk*4+1] == 0u) ? 1.0f : conj_direct(W, x, b, r0+1);
                o.z = (s_w[chunk*4+2] == 0u) ? 1.0f : conj_direct(W, x, b, r0+2);
                o.w = (s_w[chunk*4+3] == 0u) ? 1.0f : conj_direct(W, x, b, r0+3);
            }
            o4[(size_t)b * 512 + rg * 8 + chunk] = o;
        }

        // Self-reset: the LAST out tile zeroes all counters. It runs strictly
        // after every g_qdone wait has completed, so no reader races the reset.
        __syncthreads();
        if (tid == 0) {
            unsigned old = atomicAdd(&g_alldone, 1u);
            if (old == NOUT - 1u) {
                ((volatile unsigned*)g_qdone)[0] = 0u;
                ((volatile unsigned*)g_qdone)[1] = 0u;
                ((volatile unsigned*)g_qdone)[2] = 0u;
                ((volatile unsigned*)g_qdone)[3] = 0u;
                *(volatile unsigned*)&g_alldone  = 0u;
                __threadfence();
            }
        }
    }
}

// ---------------------------------------------------------------------------
extern "C" void kernel_launch(void* const* d_in, const int* in_sizes, int n_in,
                              void* d_out, int out_size) {
    const float* x = (const float*)d_in[0];   // [BATCH, IN_DIM]
    const float* W = (const float*)d_in[1];   // [IN_DIM, N_RULES]
    float* out = (float*)d_out;               // [BATCH, N_RULES]

    (void)in_sizes; (void)n_in; (void)out_size;

    fused_kernel<<<NWP + NOUT, 256>>>(W, x, out);   // single launch
}

// round 16
// speedup vs baseline: 1.2539x; 1.2539x over previous
#include <cuda_runtime.h>
#include <stdint.h>

// Problem shape (fixed by the dataset)
#define BATCH   8192
#define IN_DIM  4096
#define N_RULES 2048
#define SPLITS  256              // k-splits of 16 rows each (256*16 = 4096)
#define ROWS_PS 16

// Scratch (device globals — no allocation allowed).
// g_part[s][r] = 1 iff any W[k,r] > 0.5 for k in split s. Fully overwritten
// every call -> replay-deterministic, no init, no atomics.
__device__ uint8_t g_part[SPLITS * N_RULES];     // 512 KB

// Cold path: recompute out[b,r] directly from W and x. res > 0 iff some k has
// W[k,r] > 0.5 AND x[b,k] != 1.0f. Early-exits; never runs for typical data.
__device__ __noinline__ float conj_direct(const float* __restrict__ W,
                                          const float* __restrict__ x,
                                          int b, int r) {
    const float* xb = x + (size_t)b * IN_DIM;
    for (int k = 0; k < IN_DIM; k++) {
        if (W[(size_t)k * N_RULES + r] > 0.5f && xb[k] != 1.0f) return 0.0f;
    }
    return 1.0f;
}

// ---------------------------------------------------------------------------
// Kernel A: pure read-reduce (identical to R14 best). Block = (split, half):
// 16 rows x 1024 rules; thread owns 4 rules: 16 INDEPENDENT coalesced float4
// loads -> register OR -> one uchar4 store. After the store, signal PDL so
// out_kernel's blocks can be scheduled while our tail drains.
// ---------------------------------------------------------------------------
__global__ __launch_bounds__(256) void wpart_kernel(const float* __restrict__ W) {
    int t  = threadIdx.x;
    int s  = blockIdx.x >> 1;            // split [0, 256)
    int h  = blockIdx.x & 1;             // rule half
    int c4 = h * 256 + t;                // float4 column [0, 512)

    const float4* W4 = reinterpret_cast<const float4*>(W);
    size_t base = (size_t)s * ROWS_PS * (N_RULES / 4) + c4;
    bool a0 = false, a1 = false, a2 = false, a3 = false;
#pragma unroll
    for (int j = 0; j < ROWS_PS; j++) {
        float4 v = W4[base + (size_t)j * (N_RULES / 4)];
        a0 |= (v.x > 0.5f);
        a1 |= (v.y > 0.5f);
        a2 |= (v.z > 0.5f);
        a3 |= (v.w > 0.5f);
    }
    uchar4 rbyte;
    rbyte.x = a0; rbyte.y = a1; rbyte.z = a2; rbyte.w = a3;
    reinterpret_cast<uchar4*>(g_part)[(size_t)s * (N_RULES / 4) + c4] = rbyte;

    // PDL: allow dependent grid to launch (visibility of our stores is
    // enforced by griddepcontrol.wait in the consumer, which waits for this
    // whole grid's memory ops).
    asm volatile("griddepcontrol.launch_dependents;");
}

// ---------------------------------------------------------------------------
// Kernel B: output [BATCH, N_RULES] (identical compute to R14). Runs as a PDL
// dependent: blocks become resident early, do index setup, then
// griddepcontrol.wait guarantees all wpart stores are visible before the fold.
// ---------------------------------------------------------------------------
__global__ __launch_bounds__(256) void out_kernel(const float* __restrict__ W,
                                                  const float* __restrict__ x,
                                                  float* __restrict__ out) {
    __shared__ uint32_t sm_red[8][32];
    __shared__ __align__(16) float s_val[32];   // empty-rule answer per rule
    __shared__ uint32_t s_w[32];                // nonzero <=> rule non-empty
    __shared__ uint32_t s_flag;
    int tid = threadIdx.x;
    int rg  = blockIdx.x & 63;                  // rule-group: 32 rules
    int b0  = (blockIdx.x >> 6) * 512;          // row-slice base
    int lane = tid & 31, wi = tid >> 5;

    // Wait for the producer grid's memory to be visible (PDL).
    asm volatile("griddepcontrol.wait;");

    {   // fold empties: warp wi covers splits [wi*32, +32), lane = rule
        uint32_t acc = 0;
#pragma unroll
        for (int i = 0; i < 32; i++) {
            acc |= g_part[(size_t)(wi * 32 + i) * N_RULES + rg * 32 + lane];
        }
        sm_red[wi][lane] = acc;
    }
    __syncthreads();
    if (tid < 32) {
        uint32_t o = sm_red[0][tid] | sm_red[1][tid] | sm_red[2][tid] |
                     sm_red[3][tid] | sm_red[4][tid] | sm_red[5][tid] |
                     sm_red[6][tid] | sm_red[7][tid];
        s_w[tid]   = o;
        s_val[tid] = (o == 0u) ? 1.0f : 0.0f;
        uint32_t any = __reduce_or_sync(0xFFFFFFFFu, o);
        if (tid == 0) s_flag = (any == 0u) ? 1u : 0u;
    }
    __syncthreads();

    bool empty  = (s_flag != 0u);
    int  chunk  = tid & 7;                      // float4 chunk within 32 rules
    int  rowoff = tid >> 3;                     // 0..31
    float4 v0 = *reinterpret_cast<const float4*>(s_val + chunk * 4);
    float4* o4 = reinterpret_cast<float4*>(out);

#pragma unroll
    for (int it = 0; it < 16; it++) {
        int b = b0 + it * 32 + rowoff;
        float4 o;
        if (empty) {
            o = v0;                             // dominant path
        } else {
            int r0 = rg * 32 + chunk * 4;
            o.x = (s_w[chunk*4+0] == 0u) ? 1.0f : conj_direct(W, x, b, r0 + 0);
            o.y = (s_w[chunk*4+1] == 0u) ? 1.0f : conj_direct(W, x, b, r0 + 1);
            o.z = (s_w[chunk*4+2] == 0u) ? 1.0f : conj_direct(W, x, b, r0 + 2);
            o.w = (s_w[chunk*4+3] == 0u) ? 1.0f : conj_direct(W, x, b, r0 + 3);
        }
        o4[(size_t)b * 512 + rg * 8 + chunk] = o;
    }
}

// ---------------------------------------------------------------------------
extern "C" void kernel_launch(void* const* d_in, const int* in_sizes, int n_in,
                              void* d_out, int out_size) {
    const float* x = (const float*)d_in[0];   // [BATCH, IN_DIM]
    const float* W = (const float*)d_in[1];   // [IN_DIM, N_RULES]
    float* out = (float*)d_out;               // [BATCH, N_RULES]

    (void)in_sizes; (void)n_in; (void)out_size;

    // Producer: normal launch on the capture (legacy default) stream.
    wpart_kernel<<<SPLITS * 2, 256>>>(W);     // 512 blocks, pure read-reduce

    // Consumer: PDL — may be scheduled while wpart drains; its
    // griddepcontrol.wait enforces the data dependency.
    {
        cudaLaunchConfig_t cfg = {};
        cfg.gridDim  = dim3(64 * 16, 1, 1);
        cfg.blockDim = dim3(256, 1, 1);
        cfg.dynamicSmemBytes = 0;
        cfg.stream = 0;                        // same (captured) stream
        cudaLaunchAttribute attr[1];
        attr[0].id = cudaLaunchAttributeProgrammaticStreamSerialization;
        attr[0].val.programmaticStreamSerializationAllowed = 1;
        cfg.attrs = attr;
        cfg.numAttrs = 1;
        cudaLaunchKernelEx(&cfg, out_kernel, W, x, out);
    }
}

// round 17
// speedup vs baseline: 1.3476x; 1.0747x over previous
#include <cuda_runtime.h>
#include <stdint.h>

// Problem shape (fixed by the dataset)
#define BATCH   8192
#define IN_DIM  4096
#define N_RULES 2048
#define SPLITS  256              // k-splits of 16 rows each (256*16 = 4096)
#define ROWS_PS 16

// Scratch (device globals — no allocation allowed).
// g_part[s][r] = 1 iff any W[k,r] > 0.5 for k in split s. Fully overwritten
// every call -> replay-deterministic, no init, no atomics.
__device__ uint8_t g_part[SPLITS * N_RULES];     // 512 KB

// Cold path: recompute out[b,r] directly from W and x. res > 0 iff some k has
// W[k,r] > 0.5 AND x[b,k] != 1.0f. Early-exits; never runs for typical data.
__device__ __noinline__ float conj_direct(const float* __restrict__ W,
                                          const float* __restrict__ x,
                                          int b, int r) {
    const float* xb = x + (size_t)b * IN_DIM;
    for (int k = 0; k < IN_DIM; k++) {
        if (W[(size_t)k * N_RULES + r] > 0.5f && xb[k] != 1.0f) return 0.0f;
    }
    return 1.0f;
}

// ---------------------------------------------------------------------------
// Kernel A: pure read-reduce (R14 structure). Block = (split s, half h):
// 16 rows x 1024 rules. Thread owns 4 consecutive rules: 16 INDEPENDENT
// coalesced float4 loads (LDG.128.CS streaming — W is touched exactly once,
// keep it out of L2's retained set) -> register OR -> one uchar4 store.
// ---------------------------------------------------------------------------
__global__ __launch_bounds__(256) void wpart_kernel(const float* __restrict__ W) {
    int t  = threadIdx.x;
    int s  = blockIdx.x >> 1;            // split [0, 256)
    int h  = blockIdx.x & 1;             // rule half
    int c4 = h * 256 + t;                // float4 column [0, 512)

    const float4* W4 = reinterpret_cast<const float4*>(W);
    size_t base = (size_t)s * ROWS_PS * (N_RULES / 4) + c4;
    bool a0 = false, a1 = false, a2 = false, a3 = false;
#pragma unroll
    for (int j = 0; j < ROWS_PS; j++) {
        float4 v = __ldcs(&W4[base + (size_t)j * (N_RULES / 4)]);  // streaming
        a0 |= (v.x > 0.5f);
        a1 |= (v.y > 0.5f);
        a2 |= (v.z > 0.5f);
        a3 |= (v.w > 0.5f);
    }
    uchar4 rbyte;
    rbyte.x = a0; rbyte.y = a1; rbyte.z = a2; rbyte.w = a3;
    reinterpret_cast<uchar4*>(g_part)[(size_t)s * (N_RULES / 4) + c4] = rbyte;
}

// ---------------------------------------------------------------------------
// Kernel B: output [BATCH, N_RULES] (R14 structure). Block owns 32 rules x
// 512 rows: fold the 256 per-split empty-bytes (8KB, L2-resident), then
// stream coalesced float4 STREAMING stores (STG.128.CS — output is never
// re-read; evict-first reduces L2 retention pressure on the write drain).
// ---------------------------------------------------------------------------
__global__ __launch_bounds__(256) void out_kernel(const float* __restrict__ W,
                                                  const float* __restrict__ x,
                                                  float* __restrict__ out) {
    __shared__ uint32_t sm_red[8][32];
    __shared__ __align__(16) float s_val[32];   // empty-rule answer per rule
    __shared__ uint32_t s_w[32];                // nonzero <=> rule non-empty
    __shared__ uint32_t s_flag;
    int tid = threadIdx.x;
    int rg  = blockIdx.x & 63;                  // rule-group: 32 rules
    int b0  = (blockIdx.x >> 6) * 512;          // row-slice base

    {   // fold empties: warp wi covers splits [wi*32, +32), lane = rule
        int lane = tid & 31, wi = tid >> 5;
        uint32_t acc = 0;
#pragma unroll
        for (int i = 0; i < 32; i++) {
            acc |= g_part[(size_t)(wi * 32 + i) * N_RULES + rg * 32 + lane];
        }
        sm_red[wi][lane] = acc;
    }
    __syncthreads();
    if (tid < 32) {
        uint32_t o = sm_red[0][tid] | sm_red[1][tid] | sm_red[2][tid] |
                     sm_red[3][tid] | sm_red[4][tid] | sm_red[5][tid] |
                     sm_red[6][tid] | sm_red[7][tid];
        s_w[tid]   = o;
        s_val[tid] = (o == 0u) ? 1.0f : 0.0f;
        uint32_t any = __reduce_or_sync(0xFFFFFFFFu, o);
        if (tid == 0) s_flag = (any == 0u) ? 1u : 0u;
    }
    __syncthreads();

    bool empty  = (s_flag != 0u);
    int  chunk  = tid & 7;                      // float4 chunk within 32 rules
    int  rowoff = tid >> 3;                     // 0..31
    float4 v0 = *reinterpret_cast<const float4*>(s_val + chunk * 4);
    float4* o4 = reinterpret_cast<float4*>(out);

#pragma unroll
    for (int it = 0; it < 16; it++) {
        int b = b0 + it * 32 + rowoff;
        float4 o;
        if (empty) {
            o = v0;                             // dominant path
        } else {
            int r0 = rg * 32 + chunk * 4;
            o.x = (s_w[chunk*4+0] == 0u) ? 1.0f : conj_direct(W, x, b, r0 + 0);
            o.y = (s_w[chunk*4+1] == 0u) ? 1.0f : conj_direct(W, x, b, r0 + 1);
            o.z = (s_w[chunk*4+2] == 0u) ? 1.0f : conj_direct(W, x, b, r0 + 2);
            o.w = (s_w[chunk*4+3] == 0u) ? 1.0f : conj_direct(W, x, b, r0 + 3);
        }
        __stcs(&o4[(size_t)b * 512 + rg * 8 + chunk], o);   // streaming store
    }
}

// ---------------------------------------------------------------------------
extern "C" void kernel_launch(void* const* d_in, const int* in_sizes, int n_in,
                              void* d_out, int out_size) {
    const float* x = (const float*)d_in[0];   // [BATCH, IN_DIM]
    const float* W = (const float*)d_in[1];   // [IN_DIM, N_RULES]
    float* out = (float*)d_out;               // [BATCH, N_RULES]

    (void)in_sizes; (void)n_in; (void)out_size;

    wpart_kernel<<<SPLITS * 2, 256>>>(W);     // 512 blocks, pure read-reduce
    out_kernel<<<64 * 16, 256>>>(W, x, out);  // 1024 blocks
}